// round 9
// baseline (speedup 1.0000x reference)
#include <cuda_runtime.h>

#define NN    192
#define GRID  128
#define NG    4                      // m-slices per block
#define NT    (NN * NG)              // 768 threads
#define MS    (NN / NG)              // 48
#define SROW  196                    // padded smem row stride (floats)
#define SGS_F (NN * SROW)            // 37632
#define XS_F  (4 * NN)               // 768
#define PT_F  (32 * NN)              // 6144
#define WS_F  576
#define SMEM_BYTES ((SGS_F + XS_F + PT_F + WS_F) * 4)   // 180,480 B

#define FMA_X2(d, a, b, c) \
    asm("fma.rn.f32x2 %0, %1, %2, %3;" : "=l"(d) : "l"(a), "l"(b), "l"(c))

// ---- device-global scratch ----
__device__ __align__(16) float g_G2[NN * NN];      // G^2
__device__ __align__(16) float2 g_U[49152];        // {u1,u2} per (vec, n), max 256 vecs
__device__ float g_P1[49152];                      // [(t*16+o)*NN+n]
__device__ float g_P2[49152];                      // [(u*32+o)*NN+n]
__device__ float g_P3[49152];                      // [(t*16+o)*NN+n]

// ---- replay-safe 2-level grid barrier (8 leaves x 16, root 8) ----
__device__ unsigned g_leaf[8 * 32];                // one counter per 128B line
__device__ unsigned g_root = 0;
__device__ volatile unsigned g_gen = 0;

__device__ __forceinline__ void gsync(int b) {
    __syncthreads();
    if (threadIdx.x == 0) {
        __threadfence();                           // release
        const unsigned gen0 = g_gen;
        unsigned* leaf = &g_leaf[(b & 7) * 32];
        if (atomicAdd(leaf, 1u) == 15u) {
            *leaf = 0u;
            __threadfence();
            if (atomicAdd(&g_root, 1u) == 7u) {
                g_root = 0u;
                __threadfence();
                g_gen = gen0 + 1u;
            }
        }
        while (g_gen == gen0) { }
        __threadfence();                           // acquire + L1D inval
    }
    __syncthreads();
}

// fill padded smem matrix from a row-major 192x192 global matrix
__device__ __forceinline__ void fill_smem(float* sgs, const float* M, int tid) {
#pragma unroll
    for (int i = tid; i < NN * (NN / 4); i += NT) {
        const int row = i / (NN / 4), q = i % (NN / 4);
        ((float4*)(sgs + row * SROW))[q] = ((const float4*)M)[row * (NN / 4) + q];
    }
}

// Partial matvec (packed f32x2): thread (n,g) covers m-slice g.
template <int V>
__device__ __forceinline__ void mvpart(const float* __restrict__ sgs,
                                       const float* __restrict__ xs,
                                       float* __restrict__ part, int n, int g) {
    unsigned long long a0[V], a1[V];
#pragma unroll
    for (int v = 0; v < V; v++) { a0[v] = 0ull; a1[v] = 0ull; }
    const ulonglong2* __restrict__ srow =
        (const ulonglong2*)(sgs + n * SROW + g * MS);
#pragma unroll
    for (int q = 0; q < MS / 4; q++) {
        const ulonglong2 s2 = srow[q];
#pragma unroll
        for (int v = 0; v < V; v++) {
            const ulonglong2 x2 =
                ((const ulonglong2*)(xs + v * NN + g * MS))[q];
            FMA_X2(a0[v], s2.x, x2.x, a0[v]);
            FMA_X2(a1[v], s2.y, x2.y, a1[v]);
        }
    }
#pragma unroll
    for (int v = 0; v < V; v++) {
        float2 f0 = *(float2*)&a0[v];
        float2 f1 = *(float2*)&a1[v];
        part[(v * NG + g) * NN + n] = (f0.x + f0.y) + (f1.x + f1.y);
    }
}

__device__ __forceinline__ float rsum(const float* __restrict__ part,
                                      int v, int n) {
    return (part[(v * NG + 0) * NN + n] + part[(v * NG + 1) * NN + n])
         + (part[(v * NG + 2) * NN + n] + part[(v * NG + 3) * NN + n]);
}

// ---------------------------------------------------------------------------
// SHIFT stage: u = M @ x0 for NP vectors/block; M = smem matrix (G or G^2).
// X0M 0: X raw (pc = t, x = X[n*32+pc]); 1: plain buffer; 6: relu(buffer).
// dstc points at g_U interleaved component (.x for G-blocks, .y for G^2).
// ---------------------------------------------------------------------------
template <int NP, int X0M>
__device__ void shift_stage(const float* __restrict__ P,
                            const float* __restrict__ sgs,
                            float* __restrict__ dstc,
                            float* xs, float* part,
                            int nvec, int n, int g, int bl) {
    const int p0 = bl * NP;
    if (p0 >= nvec) return;
#pragma unroll
    for (int j = g; j < NP; j += NG) {
        const int pc = p0 + j;
        float v;
        if (X0M == 0)      v = P[n * 32 + pc];
        else if (X0M == 1) v = P[pc * NN + n];
        else             { v = P[pc * NN + n]; v = v > 0.0f ? v : 0.0f; }
        xs[j * NN + n] = v;
    }
    __syncthreads();
    mvpart<NP>(sgs, xs, part, n, g);
    __syncthreads();
    if (g < NP)
        dstc[((p0 + g) * NN + n) * 2] = rsum(part, g, n);
}

// G^2 rows 3*bg..3*bg+2: G2[r][j] = sum_m G[r][m] * G[m][j]; thread (j=n, g).
__device__ void compute_g2(const float* __restrict__ sgs, float* part,
                           int n, int g, int bg) {
    const int r0 = bg * 3;
    float acc0 = 0.f, acc1 = 0.f, acc2 = 0.f;
    for (int m = g * MS; m < g * MS + MS; m++) {
        const float gm = sgs[m * SROW + n];
        acc0 = fmaf(sgs[(r0 + 0) * SROW + m], gm, acc0);
        acc1 = fmaf(sgs[(r0 + 1) * SROW + m], gm, acc1);
        acc2 = fmaf(sgs[(r0 + 2) * SROW + m], gm, acc2);
    }
    part[(0 * NG + g) * NN + n] = acc0;
    part[(1 * NG + g) * NN + n] = acc1;
    part[(2 * NG + g) * NN + n] = acc2;
    __syncthreads();
    if (g < 3) g_G2[(r0 + g) * NN + n] = rsum(part, g, n);
}

// 9 coefficients: y(t) contributions of {x0,u1,u2} at {t, t-1, t-2}
__device__ __forceinline__ void calc_w(float h0, float h1, float h2,
                                       const float* sp, float* w) {
    w[0] = h0 + h1 * sp[0] + h2 * sp[4];
    w[1] = h1 * sp[1] + 2.0f * h2 * sp[5];
    w[2] = h2 * sp[6];
    w[3] = h1 * sp[2] + 2.0f * h2 * sp[7];
    w[4] = h1 * sp[3] + 2.0f * h2 * sp[8];
    w[5] = 2.0f * h2 * sp[9];
    w[6] = h2 * sp[10];
    w[7] = 2.0f * h2 * sp[11];
    w[8] = h2 * sp[12];
}

// ---------------------------------------------------------------------------
// proj1 (enc1): CIN=1, COUT=16, T=32, pool+relu -> g_P1. Blocks 0..15.
// ---------------------------------------------------------------------------
__device__ void proj1(const float* __restrict__ X, const float* __restrict__ h,
                      const float* sp, float* wsg, float* part,
                      int n, int g, int b) {
    if (b >= 16) return;
    if (threadIdx.x < 16)
        calc_w(h[threadIdx.x * 3], h[threadIdx.x * 3 + 1],
               h[threadIdx.x * 3 + 2], sp, &wsg[threadIdx.x * 9]);
    __syncthreads();

    const float2* __restrict__ U = g_U;
    if (g < 2) {
        const int t = b * 2 + g, tm1 = (t + 31) & 31, tm2 = (t + 30) & 31;
        const float x0t = X[n * 32 + t];
        const float x0m = X[n * 32 + tm1];
        const float x0p = X[n * 32 + tm2];
        const float2 ut = U[t * NN + n];
        const float2 um = U[tm1 * NN + n];
        const float2 up = U[tm2 * NN + n];
#pragma unroll
        for (int o = 0; o < 16; o++) {
            const float* w = &wsg[o * 9];
            float y = w[0] * x0t + w[1] * ut.x + w[2] * ut.y
                    + w[3] * x0m + w[4] * um.x + w[5] * um.y
                    + w[6] * x0p + w[7] * up.x + w[8] * up.y;
            part[(g * 16 + o) * NN + n] = y;
        }
    }
    __syncthreads();
    if (g == 0) {
#pragma unroll
        for (int o = 0; o < 16; o++) {
            float y = fmaxf(part[o * NN + n], part[(16 + o) * NN + n]);
            g_P1[(b * 16 + o) * NN + n] = fmaxf(y, 0.0f);
        }
    }
}

// ---------------------------------------------------------------------------
// proj2 (enc2): CIN=16, COUT=32, T=16, pool+relu -> g_P2. 128 items.
// Groups: q = t-parity (g>>1), ch = c-half (g&1).
// ---------------------------------------------------------------------------
__device__ void proj2(const float* __restrict__ h, const float* sp,
                      float* wsg, float* part, int n, int g, int b) {
    const int og = b & 15, ti = b >> 4, o0 = og * 2;
    if (threadIdx.x < 32) {
        const int o = threadIdx.x >> 4, c = threadIdx.x & 15;
        const float* hp = &h[((o0 + o) * 16 + c) * 3];
        calc_w(hp[0], hp[1], hp[2], sp, &wsg[(o * 16 + c) * 9]);
    }
    __syncthreads();

    const int q = g >> 1, ch = g & 1;
    const int t = ti * 2 + q, tm1 = (t + 15) & 15, tm2 = (t + 14) & 15;
    const float2* __restrict__ U = g_U;
    float y0 = 0.f, y1 = 0.f;
#pragma unroll
    for (int cc = 0; cc < 8; cc++) {
        const int c = ch * 8 + cc;
        const float x0t = g_P1[(t * 16 + c) * NN + n];
        const float x0m = g_P1[(tm1 * 16 + c) * NN + n];
        const float x0p = g_P1[(tm2 * 16 + c) * NN + n];
        const float2 ut = U[(t * 16 + c) * NN + n];
        const float2 um = U[(tm1 * 16 + c) * NN + n];
        const float2 up = U[(tm2 * 16 + c) * NN + n];
        const float* w0 = &wsg[c * 9];
        const float* w1 = &wsg[(16 + c) * 9];
        y0 += w0[0] * x0t + w0[1] * ut.x + w0[2] * ut.y
            + w0[3] * x0m + w0[4] * um.x + w0[5] * um.y
            + w0[6] * x0p + w0[7] * up.x + w0[8] * up.y;
        y1 += w1[0] * x0t + w1[1] * ut.x + w1[2] * ut.y
            + w1[3] * x0m + w1[4] * um.x + w1[5] * um.y
            + w1[6] * x0p + w1[7] * up.x + w1[8] * up.y;
    }
    part[(g * 2 + 0) * NN + n] = y0;
    part[(g * 2 + 1) * NN + n] = y1;
    __syncthreads();
    if (g == 0) {
#pragma unroll
        for (int o = 0; o < 2; o++) {
            const float ya = part[(0 + o) * NN + n] + part[(2 + o) * NN + n];
            const float yb = part[(4 + o) * NN + n] + part[(6 + o) * NN + n];
            g_P2[(ti * 32 + o0 + o) * NN + n] = fmaxf(fmaxf(ya, yb), 0.0f);
        }
    }
}

// ---------------------------------------------------------------------------
// proj3 (dec1): CIN=32, COUT=16, T=16, plain -> g_P3. x0 = up2+relu(g_P2).
// 128 items = (t, og). Groups split c into quarters. Decoder time-sparsity.
// ---------------------------------------------------------------------------
__device__ void proj3(const float* __restrict__ h, const float* sp,
                      float* wsg, float* part, int n, int g, int b) {
    const int og = b & 7, t = b >> 3, o0 = og * 2;
    if (threadIdx.x < 64) {
        const int o = threadIdx.x >> 5, c = threadIdx.x & 31;
        const float* hp = &h[((o0 + o) * 32 + c) * 3];
        calc_w(hp[0], hp[1], hp[2], sp, &wsg[(o * 32 + c) * 9]);
    }
    __syncthreads();

    const float2* __restrict__ U = g_U;
    float y0 = 0.f, y1 = 0.f;
    if (t & 1) {
        const int u = ((t + 15) & 15) >> 1;   // only t-1 even
#pragma unroll
        for (int cc = 0; cc < 8; cc++) {
            const int c = g * 8 + cc;
            float x0 = g_P2[(u * 32 + c) * NN + n]; x0 = x0 > 0.f ? x0 : 0.f;
            const float2 uv = U[(u * 32 + c) * NN + n];
            const float* w0 = &wsg[c * 9];
            const float* w1 = &wsg[(32 + c) * 9];
            y0 += w0[3] * x0 + w0[4] * uv.x + w0[5] * uv.y;
            y1 += w1[3] * x0 + w1[4] * uv.x + w1[5] * uv.y;
        }
    } else {
        const int ua = t >> 1;                // t even
        const int ub = ((t + 14) & 15) >> 1;  // t-2 even
#pragma unroll
        for (int cc = 0; cc < 8; cc++) {
            const int c = g * 8 + cc;
            float xa = g_P2[(ua * 32 + c) * NN + n]; xa = xa > 0.f ? xa : 0.f;
            float xb = g_P2[(ub * 32 + c) * NN + n]; xb = xb > 0.f ? xb : 0.f;
            const float2 uva = U[(ua * 32 + c) * NN + n];
            const float2 uvb = U[(ub * 32 + c) * NN + n];
            const float* w0 = &wsg[c * 9];
            const float* w1 = &wsg[(32 + c) * 9];
            y0 += w0[0] * xa + w0[1] * uva.x + w0[2] * uva.y
                + w0[6] * xb + w0[7] * uvb.x + w0[8] * uvb.y;
            y1 += w1[0] * xa + w1[1] * uva.x + w1[2] * uva.y
                + w1[6] * xb + w1[7] * uvb.x + w1[8] * uvb.y;
        }
    }
    part[(g * 2 + 0) * NN + n] = y0;
    part[(g * 2 + 1) * NN + n] = y1;
    __syncthreads();
    if (g == 0) {
#pragma unroll
        for (int o = 0; o < 2; o++) {
            float y = (part[(0 + o) * NN + n] + part[(2 + o) * NN + n])
                    + (part[(4 + o) * NN + n] + part[(6 + o) * NN + n]);
            g_P3[(t * 16 + o0 + o) * NN + n] = y;
        }
    }
}

// ---------------------------------------------------------------------------
// proj4 (dec2): CIN=16, COUT=1, T=32, transpose -> out. x0 = up2+relu(g_P3).
// Blocks 0..31 (one t each); groups split c into quarters (4 c each).
// ---------------------------------------------------------------------------
__device__ void proj4(const float* __restrict__ h, float* __restrict__ outp,
                      const float* sp, float* wsg, float* part,
                      int n, int g, int b) {
    if (b >= 32) return;
    if (threadIdx.x < 16)
        calc_w(h[threadIdx.x * 3], h[threadIdx.x * 3 + 1],
               h[threadIdx.x * 3 + 2], sp, &wsg[threadIdx.x * 9]);
    __syncthreads();

    const int t = b;
    const float2* __restrict__ U = g_U;
    float y = 0.f;
    if (t & 1) {
        const int u = ((t + 31) & 31) >> 1;
#pragma unroll
        for (int cc = 0; cc < 4; cc++) {
            const int c = g * 4 + cc;
            float x0 = g_P3[(u * 16 + c) * NN + n]; x0 = x0 > 0.f ? x0 : 0.f;
            const float2 uv = U[(u * 16 + c) * NN + n];
            const float* w = &wsg[c * 9];
            y += w[3] * x0 + w[4] * uv.x + w[5] * uv.y;
        }
    } else {
        const int ua = t >> 1;
        const int ub = ((t + 30) & 31) >> 1;
#pragma unroll
        for (int cc = 0; cc < 4; cc++) {
            const int c = g * 4 + cc;
            float xa = g_P3[(ua * 16 + c) * NN + n]; xa = xa > 0.f ? xa : 0.f;
            float xb = g_P3[(ub * 16 + c) * NN + n]; xb = xb > 0.f ? xb : 0.f;
            const float2 uva = U[(ua * 16 + c) * NN + n];
            const float2 uvb = U[(ub * 16 + c) * NN + n];
            const float* w = &wsg[c * 9];
            y += w[0] * xa + w[1] * uva.x + w[2] * uva.y
               + w[6] * xb + w[7] * uvb.x + w[8] * uvb.y;
        }
    }
    part[g * NN + n] = y;
    __syncthreads();
    if (g == 0)
        outp[n * 32 + t] = (part[n] + part[NN + n])
                         + (part[2 * NN + n] + part[3 * NN + n]);
}

// ---------------------------------------------------------------------------
// Single fused kernel: blocks 0..63 hold G in smem; 64..127 hold G^2.
// ---------------------------------------------------------------------------
extern __shared__ float sm[];
__global__ void __launch_bounds__(NT, 1)
fused(const float* __restrict__ X,  const float* __restrict__ Sg,
      const float* __restrict__ s4,
      const float* __restrict__ he1, const float* __restrict__ he2,
      const float* __restrict__ hd1, const float* __restrict__ hd2,
      float* __restrict__ out) {
    const int tid = threadIdx.x;
    const int g   = tid / NN;
    const int n   = tid % NN;
    const int b   = blockIdx.x;
    const bool isg2 = (b >= 64);
    const int bl  = isg2 ? b - 64 : b;
    float* dstc   = ((float*)g_U) + (isg2 ? 1 : 0);

    float* sgs  = sm;
    float* xs   = sm + SGS_F;
    float* part = xs + XS_F;
    float* wsg  = part + PT_F;

    fill_smem(sgs, Sg, tid);
    __syncthreads();

    const float s00 = s4[0], s01 = s4[1], s10 = s4[2], s11 = s4[3];
    float sp[13];
    sp[0] = s00; sp[1] = s01; sp[2] = s10; sp[3] = s11;
    sp[4] = s00 * s00; sp[5] = s00 * s01; sp[6] = s01 * s01;
    sp[7] = s00 * s10; sp[8] = s00 * s11 + s01 * s10; sp[9] = s01 * s11;
    sp[10] = s10 * s10; sp[11] = s10 * s11; sp[12] = s11 * s11;

    // S0: G-blocks start enc1 u1; G^2-blocks compute G^2 -> global.
    if (!isg2) shift_stage<1, 0>(X, sgs, dstc, xs, part, 32, n, g, bl);
    else       compute_g2(sgs, part, n, g, bl);
    gsync(b);

    // S1: G^2-blocks refill smem with G^2, then enc1 u2.
    if (isg2) {
        fill_smem(sgs, g_G2, tid);
        __syncthreads();
        shift_stage<1, 0>(X, sgs, dstc, xs, part, 32, n, g, bl);
    }
    gsync(b);

    proj1(X, he1, sp, wsg, part, n, g, b);
    gsync(b);

    // enc2 shift: 256 vectors (t*16+c), x0 = P1
    shift_stage<4, 1>(g_P1, sgs, dstc, xs, part, 256, n, g, bl);
    gsync(b);
    proj2(he2, sp, wsg, part, n, g, b);
    gsync(b);

    // dec1 shift: 256 vectors (u*32+c), x0 = relu(P2)
    shift_stage<4, 6>(g_P2, sgs, dstc, xs, part, 256, n, g, bl);
    gsync(b);
    proj3(hd1, sp, wsg, part, n, g, b);
    gsync(b);

    // dec2 shift: 256 vectors (u*16+c), x0 = relu(P3)
    shift_stage<4, 6>(g_P3, sgs, dstc, xs, part, 256, n, g, bl);
    gsync(b);
    proj4(hd2, out, sp, wsg, part, n, g, b);
}

extern "C" void kernel_launch(void* const* d_in, const int* in_sizes, int n_in,
                              void* d_out, int out_size) {
    const float* X   = (const float*)d_in[0];  // (192, 32)
    const float* Sg  = (const float*)d_in[1];  // (192, 192)
    const float* s   = (const float*)d_in[2];  // (2, 2)
    const float* he1 = (const float*)d_in[3];  // (16, 1, 3)
    const float* he2 = (const float*)d_in[4];  // (32, 16, 3)
    const float* hd1 = (const float*)d_in[5];  // (16, 32, 3)
    const float* hd2 = (const float*)d_in[6];  // (1, 16, 3)
    float* out = (float*)d_out;                // (192, 32)

    cudaFuncSetAttribute(fused, cudaFuncAttributeMaxDynamicSharedMemorySize,
                         SMEM_BYTES);
    fused<<<GRID, NT, SMEM_BYTES>>>(X, Sg, s, he1, he2, hd1, hd2, out);
}

// round 10
// speedup vs baseline: 1.0934x; 1.0934x over previous
#include <cuda_runtime.h>

#define NN    192
#define GRID  128
#define NG    4                      // m-slices / work-split groups per block
#define NT    (NN * NG)              // 768 threads
#define MS    (NN / NG)              // 48 m per slice
#define SROW  196                    // padded smem row stride (floats)
#define SGS_F (NN * SROW)            // 37632
#define XS_F  (8 * NN)
#define PT_F  (32 * NN)              // partials (proj1 needs 32 slots)
#define HS_F  192
#define SMEM_BYTES ((SGS_F + XS_F + PT_F + HS_F) * 4)   // 182,016 B

#define FMA_X2(d, a, b, c) \
    asm("fma.rn.f32x2 %0, %1, %2, %3;" : "=l"(d) : "l"(a), "l"(b), "l"(c))

// ---- device-global scratch ----
__device__ float g_XG[196608];  // interleaved {x1, g1} per (pair, n)
__device__ float g_P1[49152];   // [(t*16+o)*NN+n]
__device__ float g_P2[49152];   // [(t*32+o)*NN+n]
__device__ float g_P3[49152];   // [(t*16+o)*NN+n]

// ---- replay-safe 2-level grid barrier (8 leaves x 16 + root 8) ----
// Flat single-counter arrival serializes 128 same-address L2 atomics
// (~27 cyc each under contention). Leaves on distinct 128B lines cut the
// arrival chain to 16 + 8 ops.
__device__ unsigned g_leaf[8 * 32];   // one counter per 128B line
__device__ unsigned g_root = 0;
__device__ volatile unsigned g_gen = 0;

__device__ __forceinline__ void gsync(int b) {
    __syncthreads();
    if (threadIdx.x == 0) {
        __threadfence();                          // release
        const unsigned gen0 = g_gen;
        unsigned* leaf = &g_leaf[(b & 7) * 32];
        if (atomicAdd(leaf, 1u) == 15u) {
            *leaf = 0u;
            __threadfence();
            if (atomicAdd(&g_root, 1u) == 7u) {
                g_root = 0u;
                __threadfence();
                g_gen = gen0 + 1u;
            }
        }
        while (g_gen == gen0) { }
        __threadfence();                          // acquire + L1D inval
    }
    __syncthreads();
}

// x0 accessor modes (see call sites)
template <int X0M>
__device__ __forceinline__ float x0get(const float* __restrict__ P,
                                       int t, int c, int n, int C) {
    if (X0M == 0) return P[n * 32 + t];
    if (X0M == 1) return P[(t * C + c) * NN + n];
    if (t & 1) return 0.0f;
    float v = P[((t >> 1) * C + c) * NN + n];
    return v > 0.0f ? v : 0.0f;
}

// Partial matvec (packed f32x2 FMA): thread (n,g) covers m-slice g.
template <int V>
__device__ __forceinline__ void mvpart(const float* __restrict__ sgs,
                                       const float* __restrict__ xs,
                                       float* __restrict__ part, int n, int g) {
    unsigned long long a0[V], a1[V];
#pragma unroll
    for (int v = 0; v < V; v++) { a0[v] = 0ull; a1[v] = 0ull; }
    const ulonglong2* __restrict__ srow =
        (const ulonglong2*)(sgs + n * SROW + g * MS);
#pragma unroll
    for (int q = 0; q < MS / 4; q++) {
        const ulonglong2 s2 = srow[q];
#pragma unroll
        for (int v = 0; v < V; v++) {
            const ulonglong2 x2 =
                ((const ulonglong2*)(xs + v * NN + g * MS))[q];
            FMA_X2(a0[v], s2.x, x2.x, a0[v]);
            FMA_X2(a1[v], s2.y, x2.y, a1[v]);
        }
    }
#pragma unroll
    for (int v = 0; v < V; v++) {
        float2 f0 = *(float2*)&a0[v];
        float2 f1 = *(float2*)&a1[v];
        part[(v * NG + g) * NN + n] = (f0.x + f0.y) + (f1.x + f1.y);
    }
}

__device__ __forceinline__ float rsum(const float* __restrict__ part,
                                      int v, int n) {
    return (part[(v * NG + 0) * NN + n] + part[(v * NG + 1) * NN + n])
         + (part[(v * NG + 2) * NN + n] + part[(v * NG + 3) * NN + n]);
}

// ---------------------------------------------------------------------------
// Encoder AB (NP pairs/block): g0(t), g0(t-1); x1 = s.(x0,g0); g1 = Sg@x1.
// ---------------------------------------------------------------------------
template <int NP, int X0M>
__device__ void ab_enc(const float* __restrict__ P, const float* __restrict__ sgs,
                       float* xs, float* part,
                       float s00, float s01, float s10, float s11,
                       int C, int T, int npairs, int n, int g, int b) {
    const int p0 = b * NP;
    if (p0 >= npairs) return;

#pragma unroll
    for (int v = g; v < 2 * NP; v += NG) {
        const int j = (v < NP) ? v : v - NP;
        const int pc = p0 + j;
        int t = pc / C;
        const int c = pc % C;
        if (v >= NP) t = (t + T - 1) % T;
        xs[v * NN + n] = x0get<X0M>(P, t, c, n, C);
    }
    __syncthreads();

    mvpart<2 * NP>(sgs, xs, part, n, g);
    __syncthreads();

    if (g < NP) {
        const int j = g;
        const float g0t = rsum(part, j, n);
        const float g0m = rsum(part, NP + j, n);
        const float x1 = s00 * xs[j * NN + n] + s01 * g0t
                       + s10 * xs[(NP + j) * NN + n] + s11 * g0m;
        xs[j * NN + n] = x1;
    }
    __syncthreads();

    mvpart<NP>(sgs, xs, part, n, g);
    __syncthreads();

    if (g < NP) {
        const int j = g;
        const float g1 = rsum(part, j, n);
        ((float2*)g_XG)[(p0 + j) * NN + n] = make_float2(xs[j * NN + n], g1);
    }
}

// ---------------------------------------------------------------------------
// Decoder AB (NP pairs/block): x0 = zero-stuff up2(+relu); g0 odd-t zero.
// ---------------------------------------------------------------------------
template <int NP>
__device__ void ab_dec(const float* __restrict__ P, const float* __restrict__ sgs,
                       float* xs, float* part,
                       float s00, float s01, float s10, float s11,
                       int C, int n, int g, int b) {
    const int p0 = b * NP;

#pragma unroll
    for (int j = g; j < NP; j += NG) {
        const int pc = p0 + j;
        const int t = pc / C, c = pc % C, u = t >> 1;
        const float v = P[(u * C + c) * NN + n];
        xs[j * NN + n] = v > 0.0f ? v : 0.0f;
    }
    __syncthreads();

    mvpart<NP>(sgs, xs, part, n, g);
    __syncthreads();

    if (g < NP) {
        const int j = g;
        const int t = (p0 + j) / C;
        const float g0 = rsum(part, j, n);
        const float ca = (t & 1) ? s10 : s00;
        const float cb = (t & 1) ? s11 : s01;
        xs[j * NN + n] = ca * xs[j * NN + n] + cb * g0;
    }
    __syncthreads();

    mvpart<NP>(sgs, xs, part, n, g);
    __syncthreads();

    if (g < NP) {
        const int j = g;
        const float g1 = rsum(part, j, n);
        ((float2*)g_XG)[(p0 + j) * NN + n] = make_float2(xs[j * NN + n], g1);
    }
}

// ---------------------------------------------------------------------------
// proj1 (enc1): CIN=1, COUT=16, T=32, pool+relu -> g_P1. 16 items (blocks 0-15).
// ---------------------------------------------------------------------------
__device__ void proj1(const float* __restrict__ X, const float* __restrict__ h,
                      float s00, float s01, float s10, float s11,
                      float* part, float* hsg, int n, int g, int b) {
    if (b >= 16) return;
    if (threadIdx.x < 48) hsg[threadIdx.x] = h[threadIdx.x];
    __syncthreads();

    const int ti = b;
    const float2* __restrict__ XG = (const float2*)g_XG;
    if (g < 2) {
        const int t = ti * 2 + g, tm = (t + 31) & 31;
        const float v0 = X[n * 32 + t];
        const float2 xgt = XG[t * NN + n];
        const float2 xgm = XG[tm * NN + n];
        const float v2 = s00 * xgt.x + s01 * xgt.y + s10 * xgm.x + s11 * xgm.y;
#pragma unroll
        for (int o = 0; o < 16; o++) {
            float y = v0 * hsg[o * 3] + xgt.x * hsg[o * 3 + 1]
                    + v2 * hsg[o * 3 + 2];
            part[(g * 16 + o) * NN + n] = y;
        }
    }
    __syncthreads();
    if (g == 0) {
#pragma unroll
        for (int o = 0; o < 16; o++) {
            float y = fmaxf(part[o * NN + n], part[(16 + o) * NN + n]);
            g_P1[(ti * 16 + o) * NN + n] = fmaxf(y, 0.0f);
        }
    }
    __syncthreads();
}

// ---------------------------------------------------------------------------
// proj2 (enc2): CIN=16, COUT=32, T=16, pool+relu -> g_P2.
// 128 items = (ti 0..7) x (og 0..15), OG=2. Groups = (t-parity, c-half).
// ---------------------------------------------------------------------------
__device__ void proj2(const float* __restrict__ h,
                      float s00, float s01, float s10, float s11,
                      float* part, float* hsg, int n, int g, int b) {
    const int og = b & 15, ti = b >> 4, o0 = og * 2;
    if (threadIdx.x < 96) hsg[threadIdx.x] = h[o0 * 48 + threadIdx.x];
    __syncthreads();

    const int q = g >> 1, ch = g & 1;
    const int t = ti * 2 + q, tm = (t + 15) & 15;
    const float2* __restrict__ XG = (const float2*)g_XG;
    float y0 = 0.0f, y1 = 0.0f;
#pragma unroll
    for (int cc = 0; cc < 8; cc++) {
        const int c = ch * 8 + cc;
        const float v0 = g_P1[(t * 16 + c) * NN + n];
        const float2 xgt = XG[(t * 16 + c) * NN + n];
        const float2 xgm = XG[(tm * 16 + c) * NN + n];
        const float v2 = s00 * xgt.x + s01 * xgt.y + s10 * xgm.x + s11 * xgm.y;
        const float* hp0 = &hsg[c * 3];
        const float* hp1 = &hsg[48 + c * 3];
        y0 = fmaf(v0, hp0[0], y0); y0 = fmaf(xgt.x, hp0[1], y0);
        y0 = fmaf(v2, hp0[2], y0);
        y1 = fmaf(v0, hp1[0], y1); y1 = fmaf(xgt.x, hp1[1], y1);
        y1 = fmaf(v2, hp1[2], y1);
    }
    part[(g * 2 + 0) * NN + n] = y0;
    part[(g * 2 + 1) * NN + n] = y1;
    __syncthreads();
    if (g == 0) {
#pragma unroll
        for (int o = 0; o < 2; o++) {
            const float ya = part[(0 * 2 + o) * NN + n] + part[(1 * 2 + o) * NN + n];
            const float yb = part[(2 * 2 + o) * NN + n] + part[(3 * 2 + o) * NN + n];
            g_P2[(ti * 32 + o0 + o) * NN + n] = fmaxf(fmaxf(ya, yb), 0.0f);
        }
    }
    __syncthreads();
}

// ---------------------------------------------------------------------------
// proj3 (dec1): CIN=32, COUT=16, T=16, plain -> g_P3. x0 = up2+relu of g_P2.
// 128 items = (t 0..15) x (og 0..7), OG=2. Groups split c into quarters.
// ---------------------------------------------------------------------------
__device__ void proj3(const float* __restrict__ h,
                      float s00, float s01, float s10, float s11,
                      float* part, float* hsg, int n, int g, int b) {
    const int og = b & 7, t = b >> 3, o0 = og * 2;
    for (int i = threadIdx.x; i < 192; i += NT) hsg[i] = h[o0 * 96 + i];
    __syncthreads();

    const int tm = (t + 15) & 15;
    const float2* __restrict__ XG = (const float2*)g_XG;
    float y0 = 0.0f, y1 = 0.0f;
#pragma unroll
    for (int cc = 0; cc < 8; cc++) {
        const int c = g * 8 + cc;
        const float v0 = x0get<5>(g_P2, t, c, n, 32);
        const float2 xgt = XG[(t * 32 + c) * NN + n];
        const float2 xgm = XG[(tm * 32 + c) * NN + n];
        const float v2 = s00 * xgt.x + s01 * xgt.y + s10 * xgm.x + s11 * xgm.y;
        const float* hp0 = &hsg[c * 3];
        const float* hp1 = &hsg[96 + c * 3];
        y0 = fmaf(v0, hp0[0], y0); y0 = fmaf(xgt.x, hp0[1], y0);
        y0 = fmaf(v2, hp0[2], y0);
        y1 = fmaf(v0, hp1[0], y1); y1 = fmaf(xgt.x, hp1[1], y1);
        y1 = fmaf(v2, hp1[2], y1);
    }
    part[(g * 2 + 0) * NN + n] = y0;
    part[(g * 2 + 1) * NN + n] = y1;
    __syncthreads();
    if (g == 0) {
#pragma unroll
        for (int o = 0; o < 2; o++) {
            float y = (part[(0 * 2 + o) * NN + n] + part[(1 * 2 + o) * NN + n])
                    + (part[(2 * 2 + o) * NN + n] + part[(3 * 2 + o) * NN + n]);
            g_P3[(t * 16 + o0 + o) * NN + n] = y;
        }
    }
    __syncthreads();
}

// ---------------------------------------------------------------------------
// proj4 (dec2): CIN=16, COUT=1, T=32, transpose -> out. x0 = up2+relu of g_P3.
// 32 items (blocks 0-31). Groups split c into quarters (4 each).
// ---------------------------------------------------------------------------
__device__ void proj4(const float* __restrict__ h, float* __restrict__ outp,
                      float s00, float s01, float s10, float s11,
                      float* part, float* hsg, int n, int g, int b) {
    if (b >= 32) return;
    if (threadIdx.x < 48) hsg[threadIdx.x] = h[threadIdx.x];
    __syncthreads();

    const int t = b, tm = (t + 31) & 31;
    const float2* __restrict__ XG = (const float2*)g_XG;
    float y = 0.0f;
#pragma unroll
    for (int cc = 0; cc < 4; cc++) {
        const int c = g * 4 + cc;
        const float v0 = x0get<5>(g_P3, t, c, n, 16);
        const float2 xgt = XG[(t * 16 + c) * NN + n];
        const float2 xgm = XG[(tm * 16 + c) * NN + n];
        const float v2 = s00 * xgt.x + s01 * xgt.y + s10 * xgm.x + s11 * xgm.y;
        const float* hp = &hsg[c * 3];
        y = fmaf(v0, hp[0], y); y = fmaf(xgt.x, hp[1], y);
        y = fmaf(v2, hp[2], y);
    }
    part[g * NN + n] = y;
    __syncthreads();
    if (g == 0) {
        outp[n * 32 + t] = (part[n] + part[NN + n])
                         + (part[2 * NN + n] + part[3 * NN + n]);
    }
    __syncthreads();
}

// ---------------------------------------------------------------------------
// Single fused kernel.
// ---------------------------------------------------------------------------
extern __shared__ float sm[];
__global__ void __launch_bounds__(NT, 1)
fused(const float* __restrict__ X,  const float* __restrict__ Sg,
      const float* __restrict__ s4,
      const float* __restrict__ he1, const float* __restrict__ he2,
      const float* __restrict__ hd1, const float* __restrict__ hd2,
      float* __restrict__ out) {
    const int tid = threadIdx.x;
    const int g   = tid / NN;
    const int n   = tid % NN;
    const int b   = blockIdx.x;

    float* sgs  = sm;
    float* xs   = sm + SGS_F;
    float* part = xs + XS_F;
    float* hsg  = part + PT_F;

    {   // Fill Sg into padded smem, float4 coalesced.
        const float4* __restrict__ src = (const float4*)Sg;
#pragma unroll
        for (int i = tid; i < NN * (NN / 4); i += NT) {
            const int row = i / (NN / 4), qq = i % (NN / 4);
            ((float4*)(sgs + row * SROW))[qq] = src[row * (NN / 4) + qq];
        }
    }
    __syncthreads();

    const float s00 = s4[0], s01 = s4[1], s10 = s4[2], s11 = s4[3];

    // ---- Encoder layer 1 ----
    ab_enc<1, 0>(X, sgs, xs, part, s00, s01, s10, s11, 1, 32, 32, n, g, b);
    gsync(b);
    proj1(X, he1, s00, s01, s10, s11, part, hsg, n, g, b);
    gsync(b);

    // ---- Encoder layer 2 ----
    ab_enc<2, 1>(g_P1, sgs, xs, part, s00, s01, s10, s11, 16, 16, 256, n, g, b);
    gsync(b);
    proj2(he2, s00, s01, s10, s11, part, hsg, n, g, b);
    gsync(b);

    // ---- Decoder layer 1 ----
    ab_dec<4>(g_P2, sgs, xs, part, s00, s01, s10, s11, 32, n, g, b);
    gsync(b);
    proj3(hd1, s00, s01, s10, s11, part, hsg, n, g, b);
    gsync(b);

    // ---- Decoder layer 2 ----
    ab_dec<4>(g_P3, sgs, xs, part, s00, s01, s10, s11, 16, n, g, b);
    gsync(b);
    proj4(hd2, out, s00, s01, s10, s11, part, hsg, n, g, b);
}

extern "C" void kernel_launch(void* const* d_in, const int* in_sizes, int n_in,
                              void* d_out, int out_size) {
    const float* X   = (const float*)d_in[0];  // (192, 32)
    const float* Sg  = (const float*)d_in[1];  // (192, 192)
    const float* s   = (const float*)d_in[2];  // (2, 2)
    const float* he1 = (const float*)d_in[3];  // (16, 1, 3)
    const float* he2 = (const float*)d_in[4];  // (32, 16, 3)
    const float* hd1 = (const float*)d_in[5];  // (16, 32, 3)
    const float* hd2 = (const float*)d_in[6];  // (1, 16, 3)
    float* out = (float*)d_out;                // (192, 32)

    cudaFuncSetAttribute(fused, cudaFuncAttributeMaxDynamicSharedMemorySize,
                         SMEM_BYTES);
    fused<<<GRID, NT, SMEM_BYTES>>>(X, Sg, s, he1, he2, hd1, hd2, out);
}

// round 11
// speedup vs baseline: 1.2002x; 1.0977x over previous
#include <cuda_runtime.h>

#define NN    192
#define GRID  128
#define NG    4                      // m-slices / work-split groups per block
#define NT    (NN * NG)              // 768 threads
#define MS    (NN / NG)              // 48 m per slice
#define SROW  196                    // padded smem row stride (floats)
#define SGS_F (NN * SROW)            // 37632
#define XS_F  (8 * NN)
#define PT_F  (48 * NN)              // partials + abproj1 y-staging
#define HS_F  192
#define SMEM_BYTES ((SGS_F + XS_F + PT_F + HS_F) * 4)   // 194,304 B

#define FMA_X2(d, a, b, c) \
    asm("fma.rn.f32x2 %0, %1, %2, %3;" : "=l"(d) : "l"(a), "l"(b), "l"(c))

// ---- device-global scratch ----
__device__ float g_XG[196608];  // interleaved {x1, g1} per (pair, n)
__device__ float g_P1[49152];   // [(t*16+o)*NN+n]
__device__ float g_P2[49152];   // [(t*32+o)*NN+n]
__device__ float g_P3[49152];   // [(t*16+o)*NN+n]

// ---- replay-safe flat grid barrier (R8-proven) ----
__device__ unsigned g_cnt = 0;
__device__ volatile unsigned g_gen = 0;

__device__ __forceinline__ void gsync() {
    __syncthreads();
    if (threadIdx.x == 0) {
        __threadfence();                          // release
        unsigned gen0 = g_gen;
        if (atomicAdd(&g_cnt, 1u) == GRID - 1) {
            g_cnt = 0;
            __threadfence();
            g_gen = gen0 + 1;
        } else {
            while (g_gen == gen0) { }
        }
        __threadfence();                          // acquire + L1D inval
    }
    __syncthreads();
}

// x0 accessor modes (see call sites)
template <int X0M>
__device__ __forceinline__ float x0get(const float* __restrict__ P,
                                       int t, int c, int n, int C) {
    if (X0M == 0) return P[n * 32 + t];
    if (X0M == 1) return P[(t * C + c) * NN + n];
    if (t & 1) return 0.0f;
    float v = P[((t >> 1) * C + c) * NN + n];
    return v > 0.0f ? v : 0.0f;
}

// Partial matvec (packed f32x2 FMA): thread (n,g) covers m-slice g.
template <int V>
__device__ __forceinline__ void mvpart(const float* __restrict__ sgs,
                                       const float* __restrict__ xs,
                                       float* __restrict__ part, int n, int g) {
    unsigned long long a0[V], a1[V];
#pragma unroll
    for (int v = 0; v < V; v++) { a0[v] = 0ull; a1[v] = 0ull; }
    const ulonglong2* __restrict__ srow =
        (const ulonglong2*)(sgs + n * SROW + g * MS);
#pragma unroll
    for (int q = 0; q < MS / 4; q++) {
        const ulonglong2 s2 = srow[q];
#pragma unroll
        for (int v = 0; v < V; v++) {
            const ulonglong2 x2 =
                ((const ulonglong2*)(xs + v * NN + g * MS))[q];
            FMA_X2(a0[v], s2.x, x2.x, a0[v]);
            FMA_X2(a1[v], s2.y, x2.y, a1[v]);
        }
    }
#pragma unroll
    for (int v = 0; v < V; v++) {
        float2 f0 = *(float2*)&a0[v];
        float2 f1 = *(float2*)&a1[v];
        part[(v * NG + g) * NN + n] = (f0.x + f0.y) + (f1.x + f1.y);
    }
}

__device__ __forceinline__ float rsum(const float* __restrict__ part,
                                      int v, int n) {
    return (part[(v * NG + 0) * NN + n] + part[(v * NG + 1) * NN + n])
         + (part[(v * NG + 2) * NN + n] + part[(v * NG + 3) * NN + n]);
}

// ---------------------------------------------------------------------------
// MERGED layer 1 (CIN=1): AB + proj + pool + relu in ONE stage, no barrier.
// Block b < 16 produces P1 output ti = b (covering t0 = 2b, t1 = 2b+1).
// Time ladder w_j = (t1 - j) mod 32, j = 0..3:
//   pass1: g0(w_j) = G @ x0(w_j), j = 0..3          (V=4)
//   x1(w_j) = s00 x0(w_j) + s01 g0(w_j) + s10 x0(w_{j+1}) + s11 g0(w_{j+1}), j=0..2
//   pass2: g1(w_j) = G @ x1(w_j), j = 0..2          (V=3)
//   x2(w_j) = s00 x1(w_j) + s01 g1(w_j) + s10 x1(w_{j+1}) + s11 g1(w_{j+1}), j=0..1
//   y(w_j)[o] = h0 x0 + h1 x1 + h2 x2 ; P1[ti][o] = relu(max_j y)
// ---------------------------------------------------------------------------
__device__ void abproj1(const float* __restrict__ X, const float* __restrict__ h,
                        const float* __restrict__ sgs,
                        float* xs, float* part, float* hsg,
                        float s00, float s01, float s10, float s11,
                        int n, int g, int b) {
    if (b >= 16) return;
    const int t1 = 2 * b + 1;

    if (threadIdx.x < 48) hsg[threadIdx.x] = h[threadIdx.x];
    // stage x0 at w_0..w_3 into xs[0..3]
#pragma unroll
    for (int v = g; v < 4; v += NG)
        xs[v * NN + n] = X[n * 32 + ((t1 - v + 32) & 31)];
    __syncthreads();

    mvpart<4>(sgs, xs, part, n, g);     // g0 partials, slots 0..15
    __syncthreads();

    if (g < 3) {                        // x1(w_g) -> xs[4+g]
        const int j = g;
        const float g0a = rsum(part, j, n);
        const float g0b = rsum(part, j + 1, n);
        xs[(4 + j) * NN + n] = s00 * xs[j * NN + n] + s01 * g0a
                             + s10 * xs[(j + 1) * NN + n] + s11 * g0b;
    }
    __syncthreads();

    mvpart<3>(sgs, xs + 4 * NN, part, n, g);   // g1 partials, slots 0..11
    __syncthreads();

    if (g < 2) {                        // y(w_g)[o] -> part slots 12..43
        const int j = g;
        const float x0  = xs[j * NN + n];
        const float x1t = xs[(4 + j) * NN + n];
        const float x1m = xs[(4 + j + 1) * NN + n];
        const float g1t = rsum(part, j, n);
        const float g1m = rsum(part, j + 1, n);
        const float x2  = s00 * x1t + s01 * g1t + s10 * x1m + s11 * g1m;
#pragma unroll
        for (int o = 0; o < 16; o++) {
            const float* hp = &hsg[o * 3];
            part[(12 + j * 16 + o) * NN + n] =
                fmaf(x0, hp[0], fmaf(x1t, hp[1], x2 * hp[2]));
        }
    }
    __syncthreads();

    if (g == 0) {
#pragma unroll
        for (int o = 0; o < 16; o++) {
            const float y = fmaxf(part[(12 + o) * NN + n],
                                  part[(28 + o) * NN + n]);
            g_P1[(b * 16 + o) * NN + n] = fmaxf(y, 0.0f);
        }
    }
}

// ---------------------------------------------------------------------------
// Encoder AB (NP pairs/block): g0(t), g0(t-1); x1 = s.(x0,g0); g1 = Sg@x1.
// ---------------------------------------------------------------------------
template <int NP, int X0M>
__device__ void ab_enc(const float* __restrict__ P, const float* __restrict__ sgs,
                       float* xs, float* part,
                       float s00, float s01, float s10, float s11,
                       int C, int T, int npairs, int n, int g, int b) {
    const int p0 = b * NP;
    if (p0 >= npairs) return;

#pragma unroll
    for (int v = g; v < 2 * NP; v += NG) {
        const int j = (v < NP) ? v : v - NP;
        const int pc = p0 + j;
        int t = pc / C;
        const int c = pc % C;
        if (v >= NP) t = (t + T - 1) % T;
        xs[v * NN + n] = x0get<X0M>(P, t, c, n, C);
    }
    __syncthreads();

    mvpart<2 * NP>(sgs, xs, part, n, g);
    __syncthreads();

    if (g < NP) {
        const int j = g;
        const float g0t = rsum(part, j, n);
        const float g0m = rsum(part, NP + j, n);
        const float x1 = s00 * xs[j * NN + n] + s01 * g0t
                       + s10 * xs[(NP + j) * NN + n] + s11 * g0m;
        xs[j * NN + n] = x1;
    }
    __syncthreads();

    mvpart<NP>(sgs, xs, part, n, g);
    __syncthreads();

    if (g < NP) {
        const int j = g;
        const float g1 = rsum(part, j, n);
        ((float2*)g_XG)[(p0 + j) * NN + n] = make_float2(xs[j * NN + n], g1);
    }
}

// ---------------------------------------------------------------------------
// Decoder AB (NP pairs/block): x0 = zero-stuff up2(+relu); g0 odd-t zero.
// ---------------------------------------------------------------------------
template <int NP>
__device__ void ab_dec(const float* __restrict__ P, const float* __restrict__ sgs,
                       float* xs, float* part,
                       float s00, float s01, float s10, float s11,
                       int C, int n, int g, int b) {
    const int p0 = b * NP;

#pragma unroll
    for (int j = g; j < NP; j += NG) {
        const int pc = p0 + j;
        const int t = pc / C, c = pc % C, u = t >> 1;
        const float v = P[(u * C + c) * NN + n];
        xs[j * NN + n] = v > 0.0f ? v : 0.0f;
    }
    __syncthreads();

    mvpart<NP>(sgs, xs, part, n, g);
    __syncthreads();

    if (g < NP) {
        const int j = g;
        const int t = (p0 + j) / C;
        const float g0 = rsum(part, j, n);
        const float ca = (t & 1) ? s10 : s00;
        const float cb = (t & 1) ? s11 : s01;
        xs[j * NN + n] = ca * xs[j * NN + n] + cb * g0;
    }
    __syncthreads();

    mvpart<NP>(sgs, xs, part, n, g);
    __syncthreads();

    if (g < NP) {
        const int j = g;
        const float g1 = rsum(part, j, n);
        ((float2*)g_XG)[(p0 + j) * NN + n] = make_float2(xs[j * NN + n], g1);
    }
}

// ---------------------------------------------------------------------------
// proj2 (enc2): CIN=16, COUT=32, T=16, pool+relu -> g_P2.
// 128 items = (ti 0..7) x (og 0..15), OG=2. Groups = (t-parity, c-half).
// ---------------------------------------------------------------------------
__device__ void proj2(const float* __restrict__ h,
                      float s00, float s01, float s10, float s11,
                      float* part, float* hsg, int n, int g, int b) {
    const int og = b & 15, ti = b >> 4, o0 = og * 2;
    if (threadIdx.x < 96) hsg[threadIdx.x] = h[o0 * 48 + threadIdx.x];
    __syncthreads();

    const int q = g >> 1, ch = g & 1;
    const int t = ti * 2 + q, tm = (t + 15) & 15;
    const float2* __restrict__ XG = (const float2*)g_XG;
    float y0 = 0.0f, y1 = 0.0f;
#pragma unroll
    for (int cc = 0; cc < 8; cc++) {
        const int c = ch * 8 + cc;
        const float v0 = g_P1[(t * 16 + c) * NN + n];
        const float2 xgt = XG[(t * 16 + c) * NN + n];
        const float2 xgm = XG[(tm * 16 + c) * NN + n];
        const float v2 = s00 * xgt.x + s01 * xgt.y + s10 * xgm.x + s11 * xgm.y;
        const float* hp0 = &hsg[c * 3];
        const float* hp1 = &hsg[48 + c * 3];
        y0 = fmaf(v0, hp0[0], y0); y0 = fmaf(xgt.x, hp0[1], y0);
        y0 = fmaf(v2, hp0[2], y0);
        y1 = fmaf(v0, hp1[0], y1); y1 = fmaf(xgt.x, hp1[1], y1);
        y1 = fmaf(v2, hp1[2], y1);
    }
    part[(g * 2 + 0) * NN + n] = y0;
    part[(g * 2 + 1) * NN + n] = y1;
    __syncthreads();
    if (g == 0) {
#pragma unroll
        for (int o = 0; o < 2; o++) {
            const float ya = part[(0 * 2 + o) * NN + n] + part[(1 * 2 + o) * NN + n];
            const float yb = part[(2 * 2 + o) * NN + n] + part[(3 * 2 + o) * NN + n];
            g_P2[(ti * 32 + o0 + o) * NN + n] = fmaxf(fmaxf(ya, yb), 0.0f);
        }
    }
    __syncthreads();
}

// ---------------------------------------------------------------------------
// proj3 (dec1): CIN=32, COUT=16, T=16, plain -> g_P3. x0 = up2+relu of g_P2.
// 128 items = (t 0..15) x (og 0..7), OG=2. Groups split c into quarters.
// ---------------------------------------------------------------------------
__device__ void proj3(const float* __restrict__ h,
                      float s00, float s01, float s10, float s11,
                      float* part, float* hsg, int n, int g, int b) {
    const int og = b & 7, t = b >> 3, o0 = og * 2;
    for (int i = threadIdx.x; i < 192; i += NT) hsg[i] = h[o0 * 96 + i];
    __syncthreads();

    const int tm = (t + 15) & 15;
    const float2* __restrict__ XG = (const float2*)g_XG;
    float y0 = 0.0f, y1 = 0.0f;
#pragma unroll
    for (int cc = 0; cc < 8; cc++) {
        const int c = g * 8 + cc;
        const float v0 = x0get<5>(g_P2, t, c, n, 32);
        const float2 xgt = XG[(t * 32 + c) * NN + n];
        const float2 xgm = XG[(tm * 32 + c) * NN + n];
        const float v2 = s00 * xgt.x + s01 * xgt.y + s10 * xgm.x + s11 * xgm.y;
        const float* hp0 = &hsg[c * 3];
        const float* hp1 = &hsg[96 + c * 3];
        y0 = fmaf(v0, hp0[0], y0); y0 = fmaf(xgt.x, hp0[1], y0);
        y0 = fmaf(v2, hp0[2], y0);
        y1 = fmaf(v0, hp1[0], y1); y1 = fmaf(xgt.x, hp1[1], y1);
        y1 = fmaf(v2, hp1[2], y1);
    }
    part[(g * 2 + 0) * NN + n] = y0;
    part[(g * 2 + 1) * NN + n] = y1;
    __syncthreads();
    if (g == 0) {
#pragma unroll
        for (int o = 0; o < 2; o++) {
            float y = (part[(0 * 2 + o) * NN + n] + part[(1 * 2 + o) * NN + n])
                    + (part[(2 * 2 + o) * NN + n] + part[(3 * 2 + o) * NN + n]);
            g_P3[(t * 16 + o0 + o) * NN + n] = y;
        }
    }
    __syncthreads();
}

// ---------------------------------------------------------------------------
// proj4 (dec2): CIN=16, COUT=1, T=32, transpose -> out. x0 = up2+relu of g_P3.
// 32 items (blocks 0-31). Groups split c into quarters (4 each).
// ---------------------------------------------------------------------------
__device__ void proj4(const float* __restrict__ h, float* __restrict__ outp,
                      float s00, float s01, float s10, float s11,
                      float* part, float* hsg, int n, int g, int b) {
    if (b >= 32) return;
    if (threadIdx.x < 48) hsg[threadIdx.x] = h[threadIdx.x];
    __syncthreads();

    const int t = b, tm = (t + 31) & 31;
    const float2* __restrict__ XG = (const float2*)g_XG;
    float y = 0.0f;
#pragma unroll
    for (int cc = 0; cc < 4; cc++) {
        const int c = g * 4 + cc;
        const float v0 = x0get<5>(g_P3, t, c, n, 16);
        const float2 xgt = XG[(t * 16 + c) * NN + n];
        const float2 xgm = XG[(tm * 16 + c) * NN + n];
        const float v2 = s00 * xgt.x + s01 * xgt.y + s10 * xgm.x + s11 * xgm.y;
        const float* hp = &hsg[c * 3];
        y = fmaf(v0, hp[0], y); y = fmaf(xgt.x, hp[1], y);
        y = fmaf(v2, hp[2], y);
    }
    part[g * NN + n] = y;
    __syncthreads();
    if (g == 0) {
        outp[n * 32 + t] = (part[n] + part[NN + n])
                         + (part[2 * NN + n] + part[3 * NN + n]);
    }
    __syncthreads();
}

// ---------------------------------------------------------------------------
// Single fused kernel: 7 stages, 6 grid barriers.
// ---------------------------------------------------------------------------
extern __shared__ float sm[];
__global__ void __launch_bounds__(NT, 1)
fused(const float* __restrict__ X,  const float* __restrict__ Sg,
      const float* __restrict__ s4,
      const float* __restrict__ he1, const float* __restrict__ he2,
      const float* __restrict__ hd1, const float* __restrict__ hd2,
      float* __restrict__ out) {
    const int tid = threadIdx.x;
    const int g   = tid / NN;
    const int n   = tid % NN;
    const int b   = blockIdx.x;

    float* sgs  = sm;
    float* xs   = sm + SGS_F;
    float* part = xs + XS_F;
    float* hsg  = part + PT_F;

    {   // Fill Sg into padded smem, float4 coalesced.
        const float4* __restrict__ src = (const float4*)Sg;
#pragma unroll
        for (int i = tid; i < NN * (NN / 4); i += NT) {
            const int row = i / (NN / 4), qq = i % (NN / 4);
            ((float4*)(sgs + row * SROW))[qq] = src[row * (NN / 4) + qq];
        }
    }
    __syncthreads();

    const float s00 = s4[0], s01 = s4[1], s10 = s4[2], s11 = s4[3];

    // ---- Layer 1 (merged AB + proj + pool + relu) ----
    abproj1(X, he1, sgs, xs, part, hsg, s00, s01, s10, s11, n, g, b);
    gsync();

    // ---- Encoder layer 2 ----
    ab_enc<2, 1>(g_P1, sgs, xs, part, s00, s01, s10, s11, 16, 16, 256, n, g, b);
    gsync();
    proj2(he2, s00, s01, s10, s11, part, hsg, n, g, b);
    gsync();

    // ---- Decoder layer 1 ----
    ab_dec<4>(g_P2, sgs, xs, part, s00, s01, s10, s11, 32, n, g, b);
    gsync();
    proj3(hd1, s00, s01, s10, s11, part, hsg, n, g, b);
    gsync();

    // ---- Decoder layer 2 ----
    ab_dec<4>(g_P3, sgs, xs, part, s00, s01, s10, s11, 16, n, g, b);
    gsync();
    proj4(hd2, out, s00, s01, s10, s11, part, hsg, n, g, b);
}

extern "C" void kernel_launch(void* const* d_in, const int* in_sizes, int n_in,
                              void* d_out, int out_size) {
    const float* X   = (const float*)d_in[0];  // (192, 32)
    const float* Sg  = (const float*)d_in[1];  // (192, 192)
    const float* s   = (const float*)d_in[2];  // (2, 2)
    const float* he1 = (const float*)d_in[3];  // (16, 1, 3)
    const float* he2 = (const float*)d_in[4];  // (32, 16, 3)
    const float* hd1 = (const float*)d_in[5];  // (16, 32, 3)
    const float* hd2 = (const float*)d_in[6];  // (1, 16, 3)
    float* out = (float*)d_out;                // (192, 32)

    cudaFuncSetAttribute(fused, cudaFuncAttributeMaxDynamicSharedMemorySize,
                         SMEM_BYTES);
    fused<<<GRID, NT, SMEM_BYTES>>>(X, Sg, s, he1, he2, hd1, hd2, out);
}

// round 12
// speedup vs baseline: 1.2731x; 1.0608x over previous
#include <cuda_runtime.h>

#define NN    192
#define GRID  128
#define NG    4                      // m-slices / work-split groups per block
#define NT    (NN * NG)              // 768 threads
#define MS    (NN / NG)              // 48 m per slice
#define SROW  196                    // padded smem row stride (floats)
#define SGS_F (NN * SROW)            // 37632
#define XS_F  (8 * NN)
#define PT_F  (48 * NN)              // partials + abproj1 y-staging
#define HS_F  192
#define SMEM_BYTES ((SGS_F + XS_F + PT_F + HS_F) * 4)   // 194,304 B

#define FMA_X2(d, a, b, c) \
    asm("fma.rn.f32x2 %0, %1, %2, %3;" : "=l"(d) : "l"(a), "l"(b), "l"(c))

// ---- device-global scratch ----
__device__ float g_XG[196608];            // enc2: interleaved {x1, g1}
__device__ __align__(16) float4 g_S[49152];  // dec: {x0relu, h0, h1, -} slots
__device__ float g_P1[49152];             // [(t*16+o)*NN+n]
__device__ float g_P2[49152];             // [(u*32+o)*NN+n]
__device__ float g_P3[49152];             // [(t*16+o)*NN+n]

// ---- replay-safe flat grid barrier (R8-proven) ----
__device__ unsigned g_cnt = 0;
__device__ volatile unsigned g_gen = 0;

__device__ __forceinline__ void gsync() {
    __syncthreads();
    if (threadIdx.x == 0) {
        __threadfence();                          // release
        unsigned gen0 = g_gen;
        if (atomicAdd(&g_cnt, 1u) == GRID - 1) {
            g_cnt = 0;
            __threadfence();
            g_gen = gen0 + 1;
        } else {
            while (g_gen == gen0) { }
        }
        __threadfence();                          // acquire + L1D inval
    }
    __syncthreads();
}

// x0 accessor (enc path)
template <int X0M>
__device__ __forceinline__ float x0get(const float* __restrict__ P,
                                       int t, int c, int n, int C) {
    if (X0M == 0) return P[n * 32 + t];
    return P[(t * C + c) * NN + n];
}

// Partial matvec (packed f32x2 FMA): thread (n,g) covers m-slice g.
template <int V>
__device__ __forceinline__ void mvpart(const float* __restrict__ sgs,
                                       const float* __restrict__ xs,
                                       float* __restrict__ part, int n, int g) {
    unsigned long long a0[V], a1[V];
#pragma unroll
    for (int v = 0; v < V; v++) { a0[v] = 0ull; a1[v] = 0ull; }
    const ulonglong2* __restrict__ srow =
        (const ulonglong2*)(sgs + n * SROW + g * MS);
#pragma unroll
    for (int q = 0; q < MS / 4; q++) {
        const ulonglong2 s2 = srow[q];
#pragma unroll
        for (int v = 0; v < V; v++) {
            const ulonglong2 x2 =
                ((const ulonglong2*)(xs + v * NN + g * MS))[q];
            FMA_X2(a0[v], s2.x, x2.x, a0[v]);
            FMA_X2(a1[v], s2.y, x2.y, a1[v]);
        }
    }
#pragma unroll
    for (int v = 0; v < V; v++) {
        float2 f0 = *(float2*)&a0[v];
        float2 f1 = *(float2*)&a1[v];
        part[(v * NG + g) * NN + n] = (f0.x + f0.y) + (f1.x + f1.y);
    }
}

__device__ __forceinline__ float rsum(const float* __restrict__ part,
                                      int v, int n) {
    return (part[(v * NG + 0) * NN + n] + part[(v * NG + 1) * NN + n])
         + (part[(v * NG + 2) * NN + n] + part[(v * NG + 3) * NN + n]);
}

// ---------------------------------------------------------------------------
// MERGED layer 1 (CIN=1): AB + proj + pool + relu in one stage (R11-proven).
// ---------------------------------------------------------------------------
__device__ void abproj1(const float* __restrict__ X, const float* __restrict__ h,
                        const float* __restrict__ sgs,
                        float* xs, float* part, float* hsg,
                        float s00, float s01, float s10, float s11,
                        int n, int g, int b) {
    if (b >= 16) return;
    const int t1 = 2 * b + 1;

    if (threadIdx.x < 48) hsg[threadIdx.x] = h[threadIdx.x];
#pragma unroll
    for (int v = g; v < 4; v += NG)
        xs[v * NN + n] = X[n * 32 + ((t1 - v + 32) & 31)];
    __syncthreads();

    mvpart<4>(sgs, xs, part, n, g);
    __syncthreads();

    if (g < 3) {
        const int j = g;
        const float g0a = rsum(part, j, n);
        const float g0b = rsum(part, j + 1, n);
        xs[(4 + j) * NN + n] = s00 * xs[j * NN + n] + s01 * g0a
                             + s10 * xs[(j + 1) * NN + n] + s11 * g0b;
    }
    __syncthreads();

    mvpart<3>(sgs, xs + 4 * NN, part, n, g);
    __syncthreads();

    if (g < 2) {
        const int j = g;
        const float x0  = xs[j * NN + n];
        const float x1t = xs[(4 + j) * NN + n];
        const float x1m = xs[(4 + j + 1) * NN + n];
        const float g1t = rsum(part, j, n);
        const float g1m = rsum(part, j + 1, n);
        const float x2  = s00 * x1t + s01 * g1t + s10 * x1m + s11 * g1m;
#pragma unroll
        for (int o = 0; o < 16; o++) {
            const float* hp = &hsg[o * 3];
            part[(12 + j * 16 + o) * NN + n] =
                fmaf(x0, hp[0], fmaf(x1t, hp[1], x2 * hp[2]));
        }
    }
    __syncthreads();

    if (g == 0) {
#pragma unroll
        for (int o = 0; o < 16; o++) {
            const float y = fmaxf(part[(12 + o) * NN + n],
                                  part[(28 + o) * NN + n]);
            g_P1[(b * 16 + o) * NN + n] = fmaxf(y, 0.0f);
        }
    }
}

// ---------------------------------------------------------------------------
// Encoder AB (NP pairs/block): g0(t), g0(t-1); x1 = s.(x0,g0); g1 = Sg@x1.
// ---------------------------------------------------------------------------
template <int NP, int X0M>
__device__ void ab_enc(const float* __restrict__ P, const float* __restrict__ sgs,
                       float* xs, float* part,
                       float s00, float s01, float s10, float s11,
                       int C, int T, int npairs, int n, int g, int b) {
    const int p0 = b * NP;
    if (p0 >= npairs) return;

#pragma unroll
    for (int v = g; v < 2 * NP; v += NG) {
        const int j = (v < NP) ? v : v - NP;
        const int pc = p0 + j;
        int t = pc / C;
        const int c = pc % C;
        if (v >= NP) t = (t + T - 1) % T;
        xs[v * NN + n] = x0get<X0M>(P, t, c, n, C);
    }
    __syncthreads();

    mvpart<2 * NP>(sgs, xs, part, n, g);
    __syncthreads();

    if (g < NP) {
        const int j = g;
        const float g0t = rsum(part, j, n);
        const float g0m = rsum(part, NP + j, n);
        const float x1 = s00 * xs[j * NN + n] + s01 * g0t
                       + s10 * xs[(NP + j) * NN + n] + s11 * g0m;
        xs[j * NN + n] = x1;
    }
    __syncthreads();

    mvpart<NP>(sgs, xs, part, n, g);
    __syncthreads();

    if (g < NP) {
        const int j = g;
        const float g1 = rsum(part, j, n);
        ((float2*)g_XG)[(p0 + j) * NN + n] = make_float2(xs[j * NN + n], g1);
    }
}

// ---------------------------------------------------------------------------
// Decoder AB in {x0, h0, h1} basis (halved work): 256 even-time (u,c) slots.
//   x0r = relu(P[u,c]); h0 = G @ x0r; h1 = G @ h0; slot -> g_S.
// NP=2 per block; 2 passes of V=2 (vs 2 passes of V=4 for 512 dup pairs).
// ---------------------------------------------------------------------------
__device__ void ab_dec_h(const float* __restrict__ P, const float* __restrict__ sgs,
                         float* xs, float* part, int C, int n, int g, int b) {
    const int p0 = b * 2;

#pragma unroll
    for (int j = g; j < 2; j += NG) {
        const float v = P[(p0 + j) * NN + n];   // pc = u*C + c directly
        xs[j * NN + n] = v > 0.0f ? v : 0.0f;
    }
    __syncthreads();

    mvpart<2>(sgs, xs, part, n, g);             // h0 partials
    __syncthreads();

    if (g < 2)
        xs[(2 + g) * NN + n] = rsum(part, g, n);   // h0 vectors -> xs[2..3]
    __syncthreads();

    mvpart<2>(sgs, xs + 2 * NN, part, n, g);    // h1 partials
    __syncthreads();

    if (g < 2) {
        const float h1 = rsum(part, g, n);
        g_S[(p0 + g) * NN + n] =
            make_float4(xs[g * NN + n], xs[(2 + g) * NN + n], h1, 0.0f);
    }
}

// ---------------------------------------------------------------------------
// proj2 (enc2): CIN=16, COUT=32, T=16, pool+relu -> g_P2 (R11-proven).
// ---------------------------------------------------------------------------
__device__ void proj2(const float* __restrict__ h,
                      float s00, float s01, float s10, float s11,
                      float* part, float* hsg, int n, int g, int b) {
    const int og = b & 15, ti = b >> 4, o0 = og * 2;
    if (threadIdx.x < 96) hsg[threadIdx.x] = h[o0 * 48 + threadIdx.x];
    __syncthreads();

    const int q = g >> 1, ch = g & 1;
    const int t = ti * 2 + q, tm = (t + 15) & 15;
    const float2* __restrict__ XG = (const float2*)g_XG;
    float y0 = 0.0f, y1 = 0.0f;
#pragma unroll
    for (int cc = 0; cc < 8; cc++) {
        const int c = ch * 8 + cc;
        const float v0 = g_P1[(t * 16 + c) * NN + n];
        const float2 xgt = XG[(t * 16 + c) * NN + n];
        const float2 xgm = XG[(tm * 16 + c) * NN + n];
        const float v2 = s00 * xgt.x + s01 * xgt.y + s10 * xgm.x + s11 * xgm.y;
        const float* hp0 = &hsg[c * 3];
        const float* hp1 = &hsg[48 + c * 3];
        y0 = fmaf(v0, hp0[0], y0); y0 = fmaf(xgt.x, hp0[1], y0);
        y0 = fmaf(v2, hp0[2], y0);
        y1 = fmaf(v0, hp1[0], y1); y1 = fmaf(xgt.x, hp1[1], y1);
        y1 = fmaf(v2, hp1[2], y1);
    }
    part[(g * 2 + 0) * NN + n] = y0;
    part[(g * 2 + 1) * NN + n] = y1;
    __syncthreads();
    if (g == 0) {
#pragma unroll
        for (int o = 0; o < 2; o++) {
            const float ya = part[(0 * 2 + o) * NN + n] + part[(1 * 2 + o) * NN + n];
            const float yb = part[(2 * 2 + o) * NN + n] + part[(3 * 2 + o) * NN + n];
            g_P2[(ti * 32 + o0 + o) * NN + n] = fmaxf(fmaxf(ya, yb), 0.0f);
        }
    }
    __syncthreads();
}

// ---------------------------------------------------------------------------
// proj3 (dec1): CIN=32, COUT=16, T=16, plain -> g_P3, from g_S slots.
// even t: slots at ua=t/2 and ub=(t-2)/2; odd t: single slot ua=(t-1)/2.
// ---------------------------------------------------------------------------
__device__ void proj3(const float* __restrict__ h,
                      float s00, float s01, float s10, float s11,
                      float* part, float* hsg, int n, int g, int b) {
    const int og = b & 7, t = b >> 3, o0 = og * 2;
    for (int i = threadIdx.x; i < 192; i += NT) hsg[i] = h[o0 * 96 + i];
    __syncthreads();

    const int ua = t >> 1;                        // (t-1)/2 for odd t
    const int ub = ((t + 14) & 15) >> 1;
    const bool odd = (t & 1);
    float y0 = 0.0f, y1 = 0.0f;
#pragma unroll
    for (int cc = 0; cc < 8; cc++) {
        const int c = g * 8 + cc;
        const float4 a = g_S[(ua * 32 + c) * NN + n];
        float x0t, x1t, g1t, x1m, g1m;
        if (odd) {
            x0t = 0.0f;
            x1t = s10 * a.x + s11 * a.y;  g1t = s10 * a.y + s11 * a.z;
            x1m = s00 * a.x + s01 * a.y;  g1m = s00 * a.y + s01 * a.z;
        } else {
            const float4 bb = g_S[(ub * 32 + c) * NN + n];
            x0t = a.x;
            x1t = s00 * a.x + s01 * a.y;  g1t = s00 * a.y + s01 * a.z;
            x1m = s10 * bb.x + s11 * bb.y; g1m = s10 * bb.y + s11 * bb.z;
        }
        const float x2 = s00 * x1t + s01 * g1t + s10 * x1m + s11 * g1m;
        const float* hp0 = &hsg[c * 3];
        const float* hp1 = &hsg[96 + c * 3];
        y0 = fmaf(x0t, hp0[0], y0); y0 = fmaf(x1t, hp0[1], y0);
        y0 = fmaf(x2,  hp0[2], y0);
        y1 = fmaf(x0t, hp1[0], y1); y1 = fmaf(x1t, hp1[1], y1);
        y1 = fmaf(x2,  hp1[2], y1);
    }
    part[(g * 2 + 0) * NN + n] = y0;
    part[(g * 2 + 1) * NN + n] = y1;
    __syncthreads();
    if (g == 0) {
#pragma unroll
        for (int o = 0; o < 2; o++) {
            float y = (part[(0 * 2 + o) * NN + n] + part[(1 * 2 + o) * NN + n])
                    + (part[(2 * 2 + o) * NN + n] + part[(3 * 2 + o) * NN + n]);
            g_P3[(t * 16 + o0 + o) * NN + n] = y;
        }
    }
    __syncthreads();
}

// ---------------------------------------------------------------------------
// proj4 (dec2): CIN=16, COUT=1, T=32, transpose -> out, from g_S slots.
// ---------------------------------------------------------------------------
__device__ void proj4(const float* __restrict__ h, float* __restrict__ outp,
                      float s00, float s01, float s10, float s11,
                      float* part, float* hsg, int n, int g, int b) {
    if (b >= 32) return;
    if (threadIdx.x < 48) hsg[threadIdx.x] = h[threadIdx.x];
    __syncthreads();

    const int t = b;
    const int ua = t >> 1;
    const int ub = ((t + 30) & 31) >> 1;
    const bool odd = (t & 1);
    float y = 0.0f;
#pragma unroll
    for (int cc = 0; cc < 4; cc++) {
        const int c = g * 4 + cc;
        const float4 a = g_S[(ua * 16 + c) * NN + n];
        float x0t, x1t, g1t, x1m, g1m;
        if (odd) {
            x0t = 0.0f;
            x1t = s10 * a.x + s11 * a.y;  g1t = s10 * a.y + s11 * a.z;
            x1m = s00 * a.x + s01 * a.y;  g1m = s00 * a.y + s01 * a.z;
        } else {
            const float4 bb = g_S[(ub * 16 + c) * NN + n];
            x0t = a.x;
            x1t = s00 * a.x + s01 * a.y;  g1t = s00 * a.y + s01 * a.z;
            x1m = s10 * bb.x + s11 * bb.y; g1m = s10 * bb.y + s11 * bb.z;
        }
        const float x2 = s00 * x1t + s01 * g1t + s10 * x1m + s11 * g1m;
        const float* hp = &hsg[c * 3];
        y = fmaf(x0t, hp[0], y); y = fmaf(x1t, hp[1], y);
        y = fmaf(x2,  hp[2], y);
    }
    part[g * NN + n] = y;
    __syncthreads();
    if (g == 0) {
        outp[n * 32 + t] = (part[n] + part[NN + n])
                         + (part[2 * NN + n] + part[3 * NN + n]);
    }
    __syncthreads();
}

// ---------------------------------------------------------------------------
// Single fused kernel: 7 stages, 6 grid barriers.
// ---------------------------------------------------------------------------
extern __shared__ float sm[];
__global__ void __launch_bounds__(NT, 1)
fused(const float* __restrict__ X,  const float* __restrict__ Sg,
      const float* __restrict__ s4,
      const float* __restrict__ he1, const float* __restrict__ he2,
      const float* __restrict__ hd1, const float* __restrict__ hd2,
      float* __restrict__ out) {
    const int tid = threadIdx.x;
    const int g   = tid / NN;
    const int n   = tid % NN;
    const int b   = blockIdx.x;

    float* sgs  = sm;
    float* xs   = sm + SGS_F;
    float* part = xs + XS_F;
    float* hsg  = part + PT_F;

    {   // Fill Sg into padded smem, float4 coalesced.
        const float4* __restrict__ src = (const float4*)Sg;
#pragma unroll
        for (int i = tid; i < NN * (NN / 4); i += NT) {
            const int row = i / (NN / 4), qq = i % (NN / 4);
            ((float4*)(sgs + row * SROW))[qq] = src[row * (NN / 4) + qq];
        }
    }
    __syncthreads();

    const float s00 = s4[0], s01 = s4[1], s10 = s4[2], s11 = s4[3];

    // ---- Layer 1 (merged AB + proj + pool + relu) ----
    abproj1(X, he1, sgs, xs, part, hsg, s00, s01, s10, s11, n, g, b);
    gsync();

    // ---- Encoder layer 2 ----
    ab_enc<2, 1>(g_P1, sgs, xs, part, s00, s01, s10, s11, 16, 16, 256, n, g, b);
    gsync();
    proj2(he2, s00, s01, s10, s11, part, hsg, n, g, b);
    gsync();

    // ---- Decoder layer 1: h-basis slots over even times (u<8, c<32) ----
    ab_dec_h(g_P2, sgs, xs, part, 32, n, g, b);
    gsync();
    proj3(hd1, s00, s01, s10, s11, part, hsg, n, g, b);
    gsync();

    // ---- Decoder layer 2: h-basis slots (u<16, c<16) ----
    ab_dec_h(g_P3, sgs, xs, part, 16, n, g, b);
    gsync();
    proj4(hd2, out, s00, s01, s10, s11, part, hsg, n, g, b);
}

extern "C" void kernel_launch(void* const* d_in, const int* in_sizes, int n_in,
                              void* d_out, int out_size) {
    const float* X   = (const float*)d_in[0];  // (192, 32)
    const float* Sg  = (const float*)d_in[1];  // (192, 192)
    const float* s   = (const float*)d_in[2];  // (2, 2)
    const float* he1 = (const float*)d_in[3];  // (16, 1, 3)
    const float* he2 = (const float*)d_in[4];  // (32, 16, 3)
    const float* hd1 = (const float*)d_in[5];  // (16, 32, 3)
    const float* hd2 = (const float*)d_in[6];  // (1, 16, 3)
    float* out = (float*)d_out;                // (192, 32)

    cudaFuncSetAttribute(fused, cudaFuncAttributeMaxDynamicSharedMemorySize,
                         SMEM_BYTES);
    fused<<<GRID, NT, SMEM_BYTES>>>(X, Sg, s, he1, he2, hd1, hd2, out);
}

// round 14
// speedup vs baseline: 1.5112x; 1.1870x over previous
#include <cuda_runtime.h>

#define NN    192
#define GRID  128
#define NG    4                      // m-slices / work-split groups per block
#define NT    (NN * NG)              // 768 threads
#define MS    (NN / NG)              // 48 m per slice
#define SROW  196                    // padded smem row stride (floats)
#define SGS_F (NN * SROW)            // 37632
#define XS_F  (8 * NN)
#define PT_F  (48 * NN)              // partials + abproj1 y-staging
#define HS_F  192
#define SMEM_BYTES ((SGS_F + XS_F + PT_F + HS_F) * 4)   // 194,304 B

#define FMA_X2(d, a, b, c) \
    asm("fma.rn.f32x2 %0, %1, %2, %3;" : "=l"(d) : "l"(a), "l"(b), "l"(c))

// ---- device-global scratch ----
__device__ float g_XG[196608];               // enc2: interleaved {x1, g1}
__device__ __align__(16) float4 g_S[49152];  // dec1 slots {x0relu, h0, h1, -}
__device__ __align__(16) float4 g_S2[49152]; // dec2 slots
__device__ float g_P1[49152];                // [(t*16+o)*NN+n]

// ---- replay-safe flat grid barrier (R8-proven) ----
__device__ unsigned g_cnt = 0;
__device__ volatile unsigned g_gen = 0;

__device__ __forceinline__ void gsync() {
    __syncthreads();
    if (threadIdx.x == 0) {
        __threadfence();                          // release
        unsigned gen0 = g_gen;
        if (atomicAdd(&g_cnt, 1u) == GRID - 1) {
            g_cnt = 0;
            __threadfence();
            g_gen = gen0 + 1;
        } else {
            while (g_gen == gen0) { }
        }
        __threadfence();                          // acquire + L1D inval
    }
    __syncthreads();
}

// Partial matvec (packed f32x2 FMA): thread (n,g) covers m-slice g.
template <int V>
__device__ __forceinline__ void mvpart(const float* __restrict__ sgs,
                                       const float* __restrict__ xs,
                                       float* __restrict__ part, int n, int g) {
    unsigned long long a0[V], a1[V];
#pragma unroll
    for (int v = 0; v < V; v++) { a0[v] = 0ull; a1[v] = 0ull; }
    const ulonglong2* __restrict__ srow =
        (const ulonglong2*)(sgs + n * SROW + g * MS);
#pragma unroll
    for (int q = 0; q < MS / 4; q++) {
        const ulonglong2 s2 = srow[q];
#pragma unroll
        for (int v = 0; v < V; v++) {
            const ulonglong2 x2 =
                ((const ulonglong2*)(xs + v * NN + g * MS))[q];
            FMA_X2(a0[v], s2.x, x2.x, a0[v]);
            FMA_X2(a1[v], s2.y, x2.y, a1[v]);
        }
    }
#pragma unroll
    for (int v = 0; v < V; v++) {
        float2 f0 = *(float2*)&a0[v];
        float2 f1 = *(float2*)&a1[v];
        part[(v * NG + g) * NN + n] = (f0.x + f0.y) + (f1.x + f1.y);
    }
}

__device__ __forceinline__ float rsum(const float* __restrict__ part,
                                      int v, int n) {
    return (part[(v * NG + 0) * NN + n] + part[(v * NG + 1) * NN + n])
         + (part[(v * NG + 2) * NN + n] + part[(v * NG + 3) * NN + n]);
}

// h-basis tail: xs[0..1] hold staged (relu'd) x0 vectors for slots p0, p0+1.
// Computes h0 = G@x0, h1 = G@h0 and writes float4 slots to dst.
__device__ __forceinline__ void hbasis_tail(const float* __restrict__ sgs,
                                            float* xs, float* part,
                                            float4* __restrict__ dst,
                                            int p0, int n, int g) {
    mvpart<2>(sgs, xs, part, n, g);               // h0 partials
    __syncthreads();
    if (g < 2) xs[(2 + g) * NN + n] = rsum(part, g, n);
    __syncthreads();
    mvpart<2>(sgs, xs + 2 * NN, part, n, g);      // h1 partials
    __syncthreads();
    if (g < 2) {
        const float h1 = rsum(part, g, n);
        dst[(p0 + g) * NN + n] =
            make_float4(xs[g * NN + n], xs[(2 + g) * NN + n], h1, 0.0f);
    }
}

// ---------------------------------------------------------------------------
// MERGED layer 1 (CIN=1): AB + proj + pool + relu in one stage (R11-proven).
// ---------------------------------------------------------------------------
__device__ void abproj1(const float* __restrict__ X, const float* __restrict__ h,
                        const float* __restrict__ sgs,
                        float* xs, float* part, float* hsg,
                        float s00, float s01, float s10, float s11,
                        int n, int g, int b) {
    if (b >= 16) return;
    const int t1 = 2 * b + 1;

    if (threadIdx.x < 48) hsg[threadIdx.x] = h[threadIdx.x];
#pragma unroll
    for (int v = g; v < 4; v += NG)
        xs[v * NN + n] = X[n * 32 + ((t1 - v + 32) & 31)];
    __syncthreads();

    mvpart<4>(sgs, xs, part, n, g);
    __syncthreads();

    if (g < 3) {
        const int j = g;
        const float g0a = rsum(part, j, n);
        const float g0b = rsum(part, j + 1, n);
        xs[(4 + j) * NN + n] = s00 * xs[j * NN + n] + s01 * g0a
                             + s10 * xs[(j + 1) * NN + n] + s11 * g0b;
    }
    __syncthreads();

    mvpart<3>(sgs, xs + 4 * NN, part, n, g);
    __syncthreads();

    if (g < 2) {
        const int j = g;
        const float x0  = xs[j * NN + n];
        const float x1t = xs[(4 + j) * NN + n];
        const float x1m = xs[(4 + j + 1) * NN + n];
        const float g1t = rsum(part, j, n);
        const float g1m = rsum(part, j + 1, n);
        const float x2  = s00 * x1t + s01 * g1t + s10 * x1m + s11 * g1m;
#pragma unroll
        for (int o = 0; o < 16; o++) {
            const float* hp = &hsg[o * 3];
            part[(12 + j * 16 + o) * NN + n] =
                fmaf(x0, hp[0], fmaf(x1t, hp[1], x2 * hp[2]));
        }
    }
    __syncthreads();

    if (g == 0) {
#pragma unroll
        for (int o = 0; o < 16; o++) {
            const float y = fmaxf(part[(12 + o) * NN + n],
                                  part[(28 + o) * NN + n]);
            g_P1[(b * 16 + o) * NN + n] = fmaxf(y, 0.0f);
        }
    }
}

// ---------------------------------------------------------------------------
// Encoder AB layer 2 (NP=2 pairs/block): g0(t), g0(t-1); x1; g1 = Sg@x1.
// ---------------------------------------------------------------------------
__device__ void ab_enc2(const float* __restrict__ P, const float* __restrict__ sgs,
                        float* xs, float* part,
                        float s00, float s01, float s10, float s11,
                        int n, int g, int b) {
    const int p0 = b * 2;
    const int C = 16, T = 16;

#pragma unroll
    for (int v = g; v < 4; v += NG) {
        const int j = v & 1;
        const int pc = p0 + j;
        int t = pc / C;
        const int c = pc % C;
        if (v >= 2) t = (t + T - 1) % T;
        xs[v * NN + n] = P[(t * C + c) * NN + n];
    }
    __syncthreads();

    mvpart<4>(sgs, xs, part, n, g);
    __syncthreads();

    if (g < 2) {
        const int j = g;
        const float g0t = rsum(part, j, n);
        const float g0m = rsum(part, 2 + j, n);
        const float x1 = s00 * xs[j * NN + n] + s01 * g0t
                       + s10 * xs[(2 + j) * NN + n] + s11 * g0m;
        xs[j * NN + n] = x1;
    }
    __syncthreads();

    mvpart<2>(sgs, xs, part, n, g);
    __syncthreads();

    if (g < 2) {
        const int j = g;
        const float g1 = rsum(part, j, n);
        ((float2*)g_XG)[(p0 + j) * NN + n] = make_float2(xs[j * NN + n], g1);
    }
}

// ---------------------------------------------------------------------------
// FUSED proj2 + dec1-ab: block (ti,og) computes pooled+relu channels
// (u=ti, c=2og, 2og+1) in-block, then immediately runs the h-basis matvecs
// for those two slots (same block owns producer and consumer roles).
// ---------------------------------------------------------------------------
__device__ void proj2_dec1(const float* __restrict__ h,
                           const float* __restrict__ sgs,
                           float s00, float s01, float s10, float s11,
                           float* xs, float* part, float* hsg,
                           int n, int g, int b) {
    const int og = b & 15, ti = b >> 4, o0 = og * 2;
    if (threadIdx.x < 96) hsg[threadIdx.x] = h[o0 * 48 + threadIdx.x];
    __syncthreads();

    const int q = g >> 1, ch = g & 1;
    const int t = ti * 2 + q, tm = (t + 15) & 15;
    const float2* __restrict__ XG = (const float2*)g_XG;
    float y0 = 0.0f, y1 = 0.0f;
#pragma unroll
    for (int cc = 0; cc < 8; cc++) {
        const int c = ch * 8 + cc;
        const float v0 = g_P1[(t * 16 + c) * NN + n];
        const float2 xgt = XG[(t * 16 + c) * NN + n];
        const float2 xgm = XG[(tm * 16 + c) * NN + n];
        const float v2 = s00 * xgt.x + s01 * xgt.y + s10 * xgm.x + s11 * xgm.y;
        const float* hp0 = &hsg[c * 3];
        const float* hp1 = &hsg[48 + c * 3];
        y0 = fmaf(v0, hp0[0], y0); y0 = fmaf(xgt.x, hp0[1], y0);
        y0 = fmaf(v2, hp0[2], y0);
        y1 = fmaf(v0, hp1[0], y1); y1 = fmaf(xgt.x, hp1[1], y1);
        y1 = fmaf(v2, hp1[2], y1);
    }
    part[(g * 2 + 0) * NN + n] = y0;
    part[(g * 2 + 1) * NN + n] = y1;
    __syncthreads();

    if (g == 0) {                      // pool + relu -> staged x0 vectors
#pragma unroll
        for (int o = 0; o < 2; o++) {
            const float ya = part[(0 * 2 + o) * NN + n] + part[(1 * 2 + o) * NN + n];
            const float yb = part[(2 * 2 + o) * NN + n] + part[(3 * 2 + o) * NN + n];
            xs[o * NN + n] = fmaxf(fmaxf(ya, yb), 0.0f);
        }
    }
    __syncthreads();

    hbasis_tail(sgs, xs, part, g_S, ti * 32 + o0, n, g);
}

// ---------------------------------------------------------------------------
// FUSED proj3 + dec2-ab: block (t,og) computes dec1 conv outputs
// (t, o=2og, 2og+1) from g_S slots, relu-stages them, runs h-basis for the
// two dec2 slots pc = t*16 + o -> g_S2.
// ---------------------------------------------------------------------------
__device__ void proj3_dec2(const float* __restrict__ h,
                           const float* __restrict__ sgs,
                           float s00, float s01, float s10, float s11,
                           float* xs, float* part, float* hsg,
                           int n, int g, int b) {
    const int og = b & 7, t = b >> 3, o0 = og * 2;
    for (int i = threadIdx.x; i < 192; i += NT) hsg[i] = h[o0 * 96 + i];
    __syncthreads();

    const int ua = t >> 1;
    const int ub = ((t + 14) & 15) >> 1;
    const bool odd = (t & 1);
    float y0 = 0.0f, y1 = 0.0f;
#pragma unroll
    for (int cc = 0; cc < 8; cc++) {
        const int c = g * 8 + cc;
        const float4 a = g_S[(ua * 32 + c) * NN + n];
        float x0t, x1t, g1t, x1m, g1m;
        if (odd) {
            x0t = 0.0f;
            x1t = s10 * a.x + s11 * a.y;  g1t = s10 * a.y + s11 * a.z;
            x1m = s00 * a.x + s01 * a.y;  g1m = s00 * a.y + s01 * a.z;
        } else {
            const float4 bb = g_S[(ub * 32 + c) * NN + n];
            x0t = a.x;
            x1t = s00 * a.x + s01 * a.y;  g1t = s00 * a.y + s01 * a.z;
            x1m = s10 * bb.x + s11 * bb.y; g1m = s10 * bb.y + s11 * bb.z;
        }
        const float x2 = s00 * x1t + s01 * g1t + s10 * x1m + s11 * g1m;
        const float* hp0 = &hsg[c * 3];
        const float* hp1 = &hsg[96 + c * 3];
        y0 = fmaf(x0t, hp0[0], y0); y0 = fmaf(x1t, hp0[1], y0);
        y0 = fmaf(x2,  hp0[2], y0);
        y1 = fmaf(x0t, hp1[0], y1); y1 = fmaf(x1t, hp1[1], y1);
        y1 = fmaf(x2,  hp1[2], y1);
    }
    part[(g * 2 + 0) * NN + n] = y0;
    part[(g * 2 + 1) * NN + n] = y1;
    __syncthreads();

    if (g == 0) {                      // combine + relu (dec2's x0 = relu(P3))
#pragma unroll
        for (int o = 0; o < 2; o++) {
            const float y = (part[(0 * 2 + o) * NN + n] + part[(1 * 2 + o) * NN + n])
                          + (part[(2 * 2 + o) * NN + n] + part[(3 * 2 + o) * NN + n]);
            xs[o * NN + n] = fmaxf(y, 0.0f);
        }
    }
    __syncthreads();

    hbasis_tail(sgs, xs, part, g_S2, t * 16 + o0, n, g);
}

// ---------------------------------------------------------------------------
// proj4 (dec2): CIN=16, COUT=1, T=32, transpose -> out, from g_S2 slots.
// ---------------------------------------------------------------------------
__device__ void proj4(const float* __restrict__ h, float* __restrict__ outp,
                      float s00, float s01, float s10, float s11,
                      float* part, float* hsg, int n, int g, int b) {
    if (b >= 32) return;
    if (threadIdx.x < 48) hsg[threadIdx.x] = h[threadIdx.x];
    __syncthreads();

    const int t = b;
    const int ua = t >> 1;
    const int ub = ((t + 30) & 31) >> 1;
    const bool odd = (t & 1);
    float y = 0.0f;
#pragma unroll
    for (int cc = 0; cc < 4; cc++) {
        const int c = g * 4 + cc;
        const float4 a = g_S2[(ua * 16 + c) * NN + n];
        float x0t, x1t, g1t, x1m, g1m;
        if (odd) {
            x0t = 0.0f;
            x1t = s10 * a.x + s11 * a.y;  g1t = s10 * a.y + s11 * a.z;
            x1m = s00 * a.x + s01 * a.y;  g1m = s00 * a.y + s01 * a.z;
        } else {
            const float4 bb = g_S2[(ub * 16 + c) * NN + n];
            x0t = a.x;
            x1t = s00 * a.x + s01 * a.y;  g1t = s00 * a.y + s01 * a.z;
            x1m = s10 * bb.x + s11 * bb.y; g1m = s10 * bb.y + s11 * bb.z;
        }
        const float x2 = s00 * x1t + s01 * g1t + s10 * x1m + s11 * g1m;
        const float* hp = &hsg[c * 3];
        y = fmaf(x0t, hp[0], y); y = fmaf(x1t, hp[1], y);
        y = fmaf(x2,  hp[2], y);
    }
    part[g * NN + n] = y;
    __syncthreads();
    if (g == 0) {
        outp[n * 32 + t] = (part[n] + part[NN + n])
                         + (part[2 * NN + n] + part[3 * NN + n]);
    }
}

// ---------------------------------------------------------------------------
// Single fused kernel: 5 stages, 4 grid barriers.
// ---------------------------------------------------------------------------
extern __shared__ float sm[];
__global__ void __launch_bounds__(NT, 1)
fused(const float* __restrict__ X,  const float* __restrict__ Sg,
      const float* __restrict__ s4,
      const float* __restrict__ he1, const float* __restrict__ he2,
      const float* __restrict__ hd1, const float* __restrict__ hd2,
      float* __restrict__ out) {
    const int tid = threadIdx.x;
    const int g   = tid / NN;
    const int n   = tid % NN;
    const int b   = blockIdx.x;

    float* sgs  = sm;
    float* xs   = sm + SGS_F;
    float* part = xs + XS_F;
    float* hsg  = part + PT_F;

    {   // Fill Sg into padded smem, float4 coalesced.
        const float4* __restrict__ src = (const float4*)Sg;
#pragma unroll
        for (int i = tid; i < NN * (NN / 4); i += NT) {
            const int row = i / (NN / 4), qq = i % (NN / 4);
            ((float4*)(sgs + row * SROW))[qq] = src[row * (NN / 4) + qq];
        }
    }
    __syncthreads();

    const float s00 = s4[0], s01 = s4[1], s10 = s4[2], s11 = s4[3];

    // S1: layer 1 (merged AB + proj + pool + relu) -> g_P1
    abproj1(X, he1, sgs, xs, part, hsg, s00, s01, s10, s11, n, g, b);
    gsync();

    // S2: encoder layer 2 AB -> g_XG
    ab_enc2(g_P1, sgs, xs, part, s00, s01, s10, s11, n, g, b);
    gsync();

    // S3: proj2 (pool+relu) fused with dec1 h-basis AB -> g_S
    proj2_dec1(he2, sgs, s00, s01, s10, s11, xs, part, hsg, n, g, b);
    gsync();

    // S4: proj3 fused with dec2 h-basis AB -> g_S2
    proj3_dec2(hd1, sgs, s00, s01, s10, s11, xs, part, hsg, n, g, b);
    gsync();

    // S5: proj4 -> out
    proj4(hd2, out, s00, s01, s10, s11, part, hsg, n, g, b);
}

extern "C" void kernel_launch(void* const* d_in, const int* in_sizes, int n_in,
                              void* d_out, int out_size) {
    const float* X   = (const float*)d_in[0];  // (192, 32)
    const float* Sg  = (const float*)d_in[1];  // (192, 192)
    const float* s   = (const float*)d_in[2];  // (2, 2)
    const float* he1 = (const float*)d_in[3];  // (16, 1, 3)
    const float* he2 = (const float*)d_in[4];  // (32, 16, 3)
    const float* hd1 = (const float*)d_in[5];  // (16, 32, 3)
    const float* hd2 = (const float*)d_in[6];  // (1, 16, 3)
    float* out = (float*)d_out;                // (192, 32)

    cudaFuncSetAttribute(fused, cudaFuncAttributeMaxDynamicSharedMemorySize,
                         SMEM_BYTES);
    fused<<<GRID, NT, SMEM_BYTES>>>(X, Sg, s, he1, he2, hd1, hd2, out);
}